// round 2
// baseline (speedup 1.0000x reference)
#include <cuda_runtime.h>
#include <math.h>

// Problem constants
#define BB    256
#define HH    6
#define NN    2048
#define MM    64
#define DIN   128
#define WFLAT 12288          // H*N
#define DCAT  12416
#define DOUT  384
#define Y_N   1152           // 3*DOUT
#define MEM_ELEMS 131072     // N*M per batch
#define OUT_MEM_TOTAL 33554432  // B*N*M

// GEMM config
#define SPLITK 16
#define KCHUNK 776           // DCAT / SPLITK
#define BKT 8
#define KITERS 97            // KCHUNK / BKT
#define BMT 64
#define BNT 64
#define ASTR2 5              // A tile stride in float2 (4 pairs + 1 pad)
#define BSTR 72              // padded B stride (floats)

// Scratch (static device memory; no allocation)
__device__ float g_Ypart[SPLITK * (size_t)BB * Y_N];  // 18.9 MB split-K partials
__device__ float g_Ks[BB * DOUT];
__device__ float g_Es[BB * DOUT];
__device__ float g_As[BB * DOUT];

__device__ __forceinline__ float f2tf(float f) {
    unsigned u;
    asm("cvt.rna.tf32.f32 %0, %1;" : "=r"(u) : "f"(f));
    return __uint_as_float(u);
}

#define MMA_TF32(c, a, b0, b1)                                                     \
    asm volatile(                                                                  \
        "mma.sync.aligned.m16n8k8.row.col.f32.tf32.tf32.f32 "                      \
        "{%0,%1,%2,%3},{%4,%5,%6,%7},{%8,%9},{%0,%1,%2,%3};"                       \
        : "+f"(c[0]), "+f"(c[1]), "+f"(c[2]), "+f"(c[3])                           \
        : "r"(a[0]), "r"(a[1]), "r"(a[2]), "r"(a[3]), "r"(b0), "r"(b1))

// ---------------------------------------------------------------------------
// K1: split-K tf32 GEMM  Y[256,1152] = x[256,12416] @ [Wk|We|Wa]
// x[b,k] = (k < 12288) ? w[b*12288+k] : inputs[b*128 + k-12288]
// grid (4, 18, 16), 128 threads
// A tile stored as float2 pairs (A[m,k], A[m,k+4]) -> LDS.64 fragment loads
// ---------------------------------------------------------------------------
__global__ __launch_bounds__(128, 6) void gemm_kernel(
    const float* __restrict__ xw, const float* __restrict__ xin,
    const float* __restrict__ Wk, const float* __restrict__ We,
    const float* __restrict__ Wa)
{
    __shared__ float2 As2[2][BMT * ASTR2];
    __shared__ float  Bs[2][BKT * BSTR];

    const int tid = threadIdx.x;
    const int mt = blockIdx.x, nt = blockIdx.y, z = blockIdx.z;
    const int m0 = mt * BMT;
    const int mat = nt / 6;
    const int n0col = (nt % 6) * BNT;
    const float* __restrict__ Wp = (mat == 0) ? Wk : ((mat == 1) ? We : Wa);
    const int k0 = z * KCHUNK;

    const int wid = tid >> 5, lane = tid & 31;
    const int g = lane >> 2, t = lane & 3;
    const int wm = (wid & 1) * 32, wn = (wid >> 1) * 32;

    // Per-thread load coordinates
    const int arow = tid >> 1;          // 0..63
    const int akf  = (tid & 1) * 4;     // 0 or 4
    const int acomp = tid & 1;          // pair component
    const int bkr = tid >> 4;           // 0..7
    const int bnf = (tid & 15) * 4;     // 0..60

    float acc[2][4][4];
#pragma unroll
    for (int i = 0; i < 2; i++)
#pragma unroll
        for (int j = 0; j < 4; j++)
#pragma unroll
            for (int q = 0; q < 4; q++) acc[i][j][q] = 0.0f;

    float4 ar, br;

#define GLOAD(it)                                                                  \
    do {                                                                           \
        int kb = k0 + (it) * BKT;                                                  \
        int kg = kb + akf;                                                         \
        if (kg < WFLAT)                                                            \
            ar = *(const float4*)(xw + (size_t)(m0 + arow) * WFLAT + kg);          \
        else                                                                       \
            ar = *(const float4*)(xin + (size_t)(m0 + arow) * DIN + (kg - WFLAT)); \
        br = *(const float4*)(Wp + (size_t)(kb + bkr) * DOUT + n0col + bnf);       \
    } while (0)

#define STS(bufb)                                                                  \
    do {                                                                           \
        float* pa = (float*)&As2[bufb][arow * ASTR2];                              \
        pa[0 * 2 + acomp] = f2tf(ar.x);                                            \
        pa[1 * 2 + acomp] = f2tf(ar.y);                                            \
        pa[2 * 2 + acomp] = f2tf(ar.z);                                            \
        pa[3 * 2 + acomp] = f2tf(ar.w);                                            \
        float* pb = &Bs[bufb][bkr * BSTR + bnf];                                   \
        pb[0] = f2tf(br.x); pb[1] = f2tf(br.y);                                    \
        pb[2] = f2tf(br.z); pb[3] = f2tf(br.w);                                    \
    } while (0)

    GLOAD(0);
    STS(0);

    for (int it = 0; it < KITERS; ++it) {
        __syncthreads();
        if (it + 1 < KITERS) GLOAD(it + 1);

        const int bf = it & 1;
        // One ko step of 8 (BKT == 8)
        unsigned af[2][4];
#pragma unroll
        for (int mf = 0; mf < 2; mf++) {
            int r0 = wm + mf * 16 + g;
            float2 v0 = As2[bf][r0 * ASTR2 + t];
            float2 v1 = As2[bf][(r0 + 8) * ASTR2 + t];
            af[mf][0] = __float_as_uint(v0.x);
            af[mf][1] = __float_as_uint(v1.x);
            af[mf][2] = __float_as_uint(v0.y);
            af[mf][3] = __float_as_uint(v1.y);
        }
        unsigned bfr[4][2];
#pragma unroll
        for (int nf = 0; nf < 4; nf++) {
            int c0 = wn + nf * 8 + g;
            bfr[nf][0] = __float_as_uint(Bs[bf][t * BSTR + c0]);
            bfr[nf][1] = __float_as_uint(Bs[bf][(t + 4) * BSTR + c0]);
        }
#pragma unroll
        for (int mf = 0; mf < 2; mf++)
#pragma unroll
            for (int nf = 0; nf < 4; nf++)
                MMA_TF32(acc[mf][nf], af[mf], bfr[nf][0], bfr[nf][1]);

        if (it + 1 < KITERS) STS((it + 1) & 1);
    }

    // Epilogue: write partial tile (deterministic, no atomics)
    float* yp = g_Ypart + (size_t)z * (BB * Y_N);
#pragma unroll
    for (int mf = 0; mf < 2; mf++) {
#pragma unroll
        for (int nf = 0; nf < 4; nf++) {
            int row = m0 + wm + mf * 16 + g;
            int col = nt * BNT + wn + nf * 8 + 2 * t;
            float2 v0 = make_float2(acc[mf][nf][0], acc[mf][nf][1]);
            float2 v1 = make_float2(acc[mf][nf][2], acc[mf][nf][3]);
            *(float2*)(yp + (size_t)row * Y_N + col) = v0;
            *(float2*)(yp + (size_t)(row + 8) * Y_N + col) = v1;
        }
    }
#undef GLOAD
#undef STS
}

// ---------------------------------------------------------------------------
// K1b: reduce split-K partials, add bias, apply sigmoid for e/a
// ---------------------------------------------------------------------------
__global__ void reduce_act_kernel(const float* __restrict__ bk,
                                  const float* __restrict__ be,
                                  const float* __restrict__ ba)
{
    int idx = blockIdx.x * blockDim.x + threadIdx.x;  // < 294912
    float s = 0.0f;
#pragma unroll
    for (int z = 0; z < SPLITK; z++)
        s += g_Ypart[(size_t)z * (BB * Y_N) + idx];
    int row = idx / Y_N;
    int col = idx - row * Y_N;
    int mat = col / DOUT;
    int c = col - mat * DOUT;
    if (mat == 0) {
        g_Ks[row * DOUT + c] = s + bk[c];
    } else if (mat == 1) {
        float v = s + be[c];
        g_Es[row * DOUT + c] = 1.0f / (1.0f + __expf(-v));
    } else {
        float v = s + ba[c];
        g_As[row * DOUT + c] = 1.0f / (1.0f + __expf(-v));
    }
}

// ---------------------------------------------------------------------------
// K2: per-batch fused cosine addressing + softmax + memory update
// grid 256, 512 threads, ~54 KB dynamic smem, 2 CTAs/SM -> one wave
// ---------------------------------------------------------------------------
#define SMEM_FLOATS (HH * NN + 3 * DOUT + 96 + 8)

__global__ __launch_bounds__(512, 2) void attn_update_kernel(
    const float* __restrict__ memory, float* __restrict__ out_mem,
    float* __restrict__ out_w)
{
    extern __shared__ float sm[];
    float* scores = sm;                       // 6*2048 = 12288
    float* kn     = scores + HH * NN;         // 384
    float* esm    = kn + DOUT;                // 384
    float* asm_   = esm + DOUT;               // 384
    float* red    = asm_ + DOUT;              // 96 (6 heads x 16 warps)
    float* redh   = red + 96;                 // 8

    const int b = blockIdx.x;
    const int tid = threadIdx.x, wid = tid >> 5, lane = tid & 31;

    // ---- Phase 0: load e/a, compute normalized k ----
    if (tid < DOUT) {
        esm[tid]  = g_Es[b * DOUT + tid];
        asm_[tid] = g_As[b * DOUT + tid];
    }
    if (wid < HH) {
        float k0 = g_Ks[b * DOUT + wid * 64 + 2 * lane];
        float k1 = g_Ks[b * DOUT + wid * 64 + 2 * lane + 1];
        float ss = k0 * k0 + k1 * k1;
#pragma unroll
        for (int o = 16; o > 0; o >>= 1) ss += __shfl_xor_sync(0xffffffffu, ss, o);
        float rn = rsqrtf(ss);
        kn[wid * 64 + 2 * lane]     = k0 * rn;
        kn[wid * 64 + 2 * lane + 1] = k1 * rn;
    }
    __syncthreads();

    const float* __restrict__ memb = memory + (size_t)b * MEM_ELEMS;

    // ---- Phase 1: scores[h][n] = cos(k_h, mem_n) ----
    // 4 rows per warp, 8 lanes per row, coalesced 1KB loads per warp step.
    {
        const int oct = lane >> 3;   // row within the warp's group of 4
        const int ol  = lane & 7;    // lane within octet
        for (int n0 = wid * 4; n0 < NN; n0 += 64) {
            int n = n0 + oct;
            const float4* rp = (const float4*)(memb + (size_t)n * MM + ol * 8);
            float4 u = rp[0];
            float4 v = rp[1];
            float ss = u.x * u.x + u.y * u.y + u.z * u.z + u.w * u.w +
                       v.x * v.x + v.y * v.y + v.z * v.z + v.w * v.w;
            float d[HH];
#pragma unroll
            for (int h = 0; h < HH; h++) {
                float4 ka = *(const float4*)(kn + h * 64 + ol * 8);
                float4 kb2 = *(const float4*)(kn + h * 64 + ol * 8 + 4);
                d[h] = u.x * ka.x + u.y * ka.y + u.z * ka.z + u.w * ka.w +
                       v.x * kb2.x + v.y * kb2.y + v.z * kb2.z + v.w * kb2.w;
            }
            // reduce over the 8-lane octet
#pragma unroll
            for (int o = 1; o < 8; o <<= 1) {
                ss += __shfl_xor_sync(0xffffffffu, ss, o);
#pragma unroll
                for (int h = 0; h < HH; h++)
                    d[h] += __shfl_xor_sync(0xffffffffu, d[h], o);
            }
            float rn = rsqrtf(ss);
            if (ol < HH) {
                float dv = (ol == 0) ? d[0] : (ol == 1) ? d[1] : (ol == 2) ? d[2]
                         : (ol == 3) ? d[3] : (ol == 4) ? d[4] : d[5];
                scores[ol * NN + n] = dv * rn;
            }
        }
    }
    __syncthreads();

    // ---- Phase 2: softmax over n, all heads fused ----
    {
        float mx[HH];
#pragma unroll
        for (int h = 0; h < HH; h++) mx[h] = -1e30f;
        for (int i = tid; i < NN; i += 512)
#pragma unroll
            for (int h = 0; h < HH; h++)
                mx[h] = fmaxf(mx[h], scores[h * NN + i]);
#pragma unroll
        for (int h = 0; h < HH; h++) {
#pragma unroll
            for (int o = 16; o > 0; o >>= 1)
                mx[h] = fmaxf(mx[h], __shfl_xor_sync(0xffffffffu, mx[h], o));
        }
        if (lane == 0)
#pragma unroll
            for (int h = 0; h < HH; h++) red[h * 16 + wid] = mx[h];
        __syncthreads();
        if (wid == 0) {
#pragma unroll
            for (int h = 0; h < HH; h++) {
                float v = (lane < 16) ? red[h * 16 + lane] : -1e30f;
#pragma unroll
                for (int o = 8; o > 0; o >>= 1)
                    v = fmaxf(v, __shfl_xor_sync(0xffffffffu, v, o));
                if (lane == 0) redh[h] = v;
            }
        }
        __syncthreads();

        float bmx[HH], sum[HH];
#pragma unroll
        for (int h = 0; h < HH; h++) { bmx[h] = redh[h]; sum[h] = 0.0f; }
        for (int i = tid; i < NN; i += 512) {
#pragma unroll
            for (int h = 0; h < HH; h++) {
                float e = __expf(scores[h * NN + i] - bmx[h]);
                scores[h * NN + i] = e;
                sum[h] += e;
            }
        }
#pragma unroll
        for (int h = 0; h < HH; h++) {
#pragma unroll
            for (int o = 16; o > 0; o >>= 1)
                sum[h] += __shfl_xor_sync(0xffffffffu, sum[h], o);
        }
        if (lane == 0)
#pragma unroll
            for (int h = 0; h < HH; h++) red[h * 16 + wid] = sum[h];
        __syncthreads();
        if (wid == 0) {
#pragma unroll
            for (int h = 0; h < HH; h++) {
                float v = (lane < 16) ? red[h * 16 + lane] : 0.0f;
#pragma unroll
                for (int o = 8; o > 0; o >>= 1)
                    v += __shfl_xor_sync(0xffffffffu, v, o);
                if (lane == 0) redh[h] = v;
            }
        }
        __syncthreads();

        float inv[HH];
#pragma unroll
        for (int h = 0; h < HH; h++) inv[h] = 1.0f / redh[h];
        for (int i = tid; i < NN; i += 512) {
#pragma unroll
            for (int h = 0; h < HH; h++) {
                float wv = scores[h * NN + i] * inv[h];
                scores[h * NN + i] = wv;
                out_w[(size_t)b * (HH * NN) + h * NN + i] = wv;
            }
        }
    }
    __syncthreads();

    // ---- Phase 3: new_mem = m - m*m*erase + add (warp per row) ----
    float eh0[HH], eh1[HH], ah0[HH], ah1[HH];
#pragma unroll
    for (int h = 0; h < HH; h++) {
        eh0[h] = esm[h * 64 + 2 * lane];
        eh1[h] = esm[h * 64 + 2 * lane + 1];
        ah0[h] = asm_[h * 64 + 2 * lane];
        ah1[h] = asm_[h * 64 + 2 * lane + 1];
    }
    float* outm = out_mem + (size_t)b * MEM_ELEMS;
    for (int n = wid; n < NN; n += 16) {
        float2 mv = *(const float2*)(memb + (size_t)n * MM + 2 * lane);
        float er0 = 0.f, er1 = 0.f, ad0 = 0.f, ad1 = 0.f;
#pragma unroll
        for (int h = 0; h < HH; h++) {
            float wv = scores[h * NN + n];
            er0 += wv * eh0[h];
            er1 += wv * eh1[h];
            ad0 += wv * ah0[h];
            ad1 += wv * ah1[h];
        }
        float2 ov;
        ov.x = mv.x - mv.x * mv.x * er0 + ad0;
        ov.y = mv.y - mv.y * mv.y * er1 + ad1;
        *(float2*)(outm + (size_t)n * MM + 2 * lane) = ov;
    }
}

// ---------------------------------------------------------------------------
extern "C" void kernel_launch(void* const* d_in, const int* in_sizes, int n_in,
                              void* d_out, int out_size)
{
    const float* inputs = (const float*)d_in[0];
    const float* memory = (const float*)d_in[1];
    const float* w      = (const float*)d_in[2];
    const float* Wk     = (const float*)d_in[3];
    const float* bk     = (const float*)d_in[4];
    const float* We     = (const float*)d_in[5];
    const float* be     = (const float*)d_in[6];
    const float* Wa     = (const float*)d_in[7];
    const float* ba     = (const float*)d_in[8];

    float* out     = (float*)d_out;
    float* out_mem = out;                       // new_memory [B,N,M]
    float* out_w   = out + OUT_MEM_TOTAL;       // w_new      [B,H,N]

    dim3 g1(4, 18, SPLITK);
    gemm_kernel<<<g1, 128>>>(w, inputs, Wk, We, Wa);

    reduce_act_kernel<<<(BB * Y_N) / 256, 256>>>(bk, be, ba);

    const int smem_bytes = SMEM_FLOATS * (int)sizeof(float);
    cudaFuncSetAttribute(attn_update_kernel,
                         cudaFuncAttributeMaxDynamicSharedMemorySize, smem_bytes);
    attn_update_kernel<<<BB, 512, smem_bytes>>>(memory, out_mem, out_w);
}

// round 3
// speedup vs baseline: 1.5093x; 1.5093x over previous
#include <cuda_runtime.h>
#include <math.h>

// Problem constants
#define BB    256
#define HH    6
#define NN    2048
#define MM    64
#define DIN   128
#define WFLAT 12288          // H*N
#define DCAT  12416
#define DOUT  384
#define Y_N   1152           // 3*DOUT
#define MEM_ELEMS 131072     // N*M per batch
#define OUT_MEM_TOTAL 33554432  // B*N*M

// GEMM config (R1 configuration — measured 95.3us)
#define SPLITK 8
#define KCHUNK 1552          // DCAT / SPLITK
#define KITERS 97            // KCHUNK / BKT
#define BKT 16
#define BMT 64
#define BNT 64
#define ASTR 20              // padded A stride (conflict-free frag loads)
#define BSTR 72              // padded B stride

// Scratch (static device memory; no allocation)
__device__ float g_Ypart[SPLITK * (size_t)BB * Y_N];
__device__ float g_Ks[BB * DOUT];
__device__ float g_Es[BB * DOUT];
__device__ float g_As[BB * DOUT];

__device__ __forceinline__ float f2tf(float f) {
    unsigned u;
    asm("cvt.rna.tf32.f32 %0, %1;" : "=r"(u) : "f"(f));
    return __uint_as_float(u);
}

#define MMA_TF32(c, a, b0, b1)                                                     \
    asm volatile(                                                                  \
        "mma.sync.aligned.m16n8k8.row.col.f32.tf32.tf32.f32 "                      \
        "{%0,%1,%2,%3},{%4,%5,%6,%7},{%8,%9},{%0,%1,%2,%3};"                       \
        : "+f"(c[0]), "+f"(c[1]), "+f"(c[2]), "+f"(c[3])                           \
        : "r"(a[0]), "r"(a[1]), "r"(a[2]), "r"(a[3]), "r"(b0), "r"(b1))

// ---------------------------------------------------------------------------
// K1: split-K tf32 GEMM  Y[256,1152] = x[256,12416] @ [Wk|We|Wa]  (R1 verbatim)
// ---------------------------------------------------------------------------
__global__ __launch_bounds__(128) void gemm_kernel(
    const float* __restrict__ xw, const float* __restrict__ xin,
    const float* __restrict__ Wk, const float* __restrict__ We,
    const float* __restrict__ Wa)
{
    __shared__ float As[2][BMT * ASTR];
    __shared__ float Bs[2][BKT * BSTR];

    const int tid = threadIdx.x;
    const int mt = blockIdx.x, nt = blockIdx.y, z = blockIdx.z;
    const int m0 = mt * BMT;
    const int mat = nt / 6;
    const int n0col = (nt % 6) * BNT;
    const float* __restrict__ Wp = (mat == 0) ? Wk : ((mat == 1) ? We : Wa);
    const int k0 = z * KCHUNK;

    const int wid = tid >> 5, lane = tid & 31;
    const int g = lane >> 2, t = lane & 3;
    const int wm = (wid & 1) * 32, wn = (wid >> 1) * 32;

    float acc[2][4][4];
#pragma unroll
    for (int i = 0; i < 2; i++)
#pragma unroll
        for (int j = 0; j < 4; j++)
#pragma unroll
            for (int q = 0; q < 4; q++) acc[i][j][q] = 0.0f;

    float4 ar[2], br[2];

#define GLOAD(it)                                                                  \
    do {                                                                           \
        int kb = k0 + (it) * BKT;                                                  \
        for (int i = 0; i < 2; i++) {                                              \
            int j = tid + i * 128;                                                 \
            int row = j >> 2;                                                      \
            int kg = kb + (j & 3) * 4;                                             \
            if (kg < WFLAT)                                                        \
                ar[i] = *(const float4*)(xw + (size_t)(m0 + row) * WFLAT + kg);    \
            else                                                                   \
                ar[i] = *(const float4*)(xin + (size_t)(m0 + row) * DIN +          \
                                         (kg - WFLAT));                            \
        }                                                                          \
        for (int i = 0; i < 2; i++) {                                              \
            int j = tid + i * 128;                                                 \
            int kr = j >> 4;                                                       \
            int nf = (j & 15) * 4;                                                 \
            br[i] = *(const float4*)(Wp + (size_t)(kb + kr) * DOUT + n0col + nf);  \
        }                                                                          \
    } while (0)

#define STS(bufb)                                                                  \
    do {                                                                           \
        for (int i = 0; i < 2; i++) {                                              \
            int j = tid + i * 128;                                                 \
            int row = j >> 2;                                                      \
            int kf = (j & 3) * 4;                                                  \
            float* p = &As[bufb][row * ASTR + kf];                                 \
            p[0] = f2tf(ar[i].x); p[1] = f2tf(ar[i].y);                            \
            p[2] = f2tf(ar[i].z); p[3] = f2tf(ar[i].w);                            \
        }                                                                          \
        for (int i = 0; i < 2; i++) {                                              \
            int j = tid + i * 128;                                                 \
            int kr = j >> 4;                                                       \
            int nf = (j & 15) * 4;                                                 \
            float* p = &Bs[bufb][kr * BSTR + nf];                                  \
            p[0] = f2tf(br[i].x); p[1] = f2tf(br[i].y);                            \
            p[2] = f2tf(br[i].z); p[3] = f2tf(br[i].w);                            \
        }                                                                          \
    } while (0)

    GLOAD(0);
    STS(0);

    for (int it = 0; it < KITERS; ++it) {
        __syncthreads();
        if (it + 1 < KITERS) GLOAD(it + 1);

        const int bf = it & 1;
#pragma unroll
        for (int ko = 0; ko < BKT; ko += 8) {
            unsigned af[2][4];
#pragma unroll
            for (int mf = 0; mf < 2; mf++) {
                int r0 = wm + mf * 16 + g;
                af[mf][0] = __float_as_uint(As[bf][r0 * ASTR + ko + t]);
                af[mf][1] = __float_as_uint(As[bf][(r0 + 8) * ASTR + ko + t]);
                af[mf][2] = __float_as_uint(As[bf][r0 * ASTR + ko + t + 4]);
                af[mf][3] = __float_as_uint(As[bf][(r0 + 8) * ASTR + ko + t + 4]);
            }
            unsigned bfr[4][2];
#pragma unroll
            for (int nf = 0; nf < 4; nf++) {
                int c0 = wn + nf * 8 + g;
                bfr[nf][0] = __float_as_uint(Bs[bf][(ko + t) * BSTR + c0]);
                bfr[nf][1] = __float_as_uint(Bs[bf][(ko + t + 4) * BSTR + c0]);
            }
#pragma unroll
            for (int mf = 0; mf < 2; mf++)
#pragma unroll
                for (int nf = 0; nf < 4; nf++)
                    MMA_TF32(acc[mf][nf], af[mf], bfr[nf][0], bfr[nf][1]);
        }

        if (it + 1 < KITERS) STS((it + 1) & 1);
    }

    float* yp = g_Ypart + (size_t)z * (BB * Y_N);
#pragma unroll
    for (int mf = 0; mf < 2; mf++) {
#pragma unroll
        for (int nf = 0; nf < 4; nf++) {
            int row = m0 + wm + mf * 16 + g;
            int col = nt * BNT + wn + nf * 8 + 2 * t;
            float2 v0 = make_float2(acc[mf][nf][0], acc[mf][nf][1]);
            float2 v1 = make_float2(acc[mf][nf][2], acc[mf][nf][3]);
            *(float2*)(yp + (size_t)row * Y_N + col) = v0;
            *(float2*)(yp + (size_t)(row + 8) * Y_N + col) = v1;
        }
    }
#undef GLOAD
#undef STS
}

// ---------------------------------------------------------------------------
// K1b: reduce split-K partials, add bias, apply sigmoid for e/a
// ---------------------------------------------------------------------------
__global__ void reduce_act_kernel(const float* __restrict__ bk,
                                  const float* __restrict__ be,
                                  const float* __restrict__ ba)
{
    int idx = blockIdx.x * blockDim.x + threadIdx.x;
    float s = 0.0f;
#pragma unroll
    for (int z = 0; z < SPLITK; z++)
        s += g_Ypart[(size_t)z * (BB * Y_N) + idx];
    int row = idx / Y_N;
    int col = idx - row * Y_N;
    int mat = col / DOUT;
    int c = col - mat * DOUT;
    if (mat == 0) {
        g_Ks[row * DOUT + c] = s + bk[c];
    } else if (mat == 1) {
        float v = s + be[c];
        g_Es[row * DOUT + c] = 1.0f / (1.0f + __expf(-v));
    } else {
        float v = s + ba[c];
        g_As[row * DOUT + c] = 1.0f / (1.0f + __expf(-v));
    }
}

// ---------------------------------------------------------------------------
// K2: per-batch fused addressing + softmax + update, tensor-core einsums.
// grid 256, 512 threads (16 warps), ~148.6 KB smem (occ 1 by design).
// ---------------------------------------------------------------------------
#define SST 9        // scores row stride (floats): conflict-free both axes
#define TSTRIDE 68   // per-warp tile row stride (floats) = 17 float4
#define ATTN_SMEM_FLOATS (NN * SST + 16 * 16 * TSTRIDE + 3 * DOUT + 6 * 16 + 8)

__global__ __launch_bounds__(512, 1) void attn_update_kernel(
    const float* __restrict__ memory, float* __restrict__ out_mem,
    float* __restrict__ out_w)
{
    extern __shared__ float sm[];
    float* scores2 = sm;                          // 2048*9
    float* tile    = scores2 + NN * SST;          // 16 warps * 16 * 68
    float* kn      = tile + 16 * 16 * TSTRIDE;    // 384
    float* esm     = kn + DOUT;                   // 384
    float* asm_    = esm + DOUT;                  // 384
    float* red     = asm_ + DOUT;                 // 96
    float* redh    = red + 96;                    // 8

    const int b = blockIdx.x;
    const int tid = threadIdx.x, wid = tid >> 5, lane = tid & 31;
    const int g = lane >> 2, t = lane & 3;

    // ---- Phase 0: load e/a, compute normalized k ----
    if (tid < DOUT) {
        esm[tid]  = g_Es[b * DOUT + tid];
        asm_[tid] = g_As[b * DOUT + tid];
    }
    if (wid < HH) {
        float k0 = g_Ks[b * DOUT + wid * 64 + 2 * lane];
        float k1 = g_Ks[b * DOUT + wid * 64 + 2 * lane + 1];
        float ss = k0 * k0 + k1 * k1;
#pragma unroll
        for (int o = 16; o > 0; o >>= 1) ss += __shfl_xor_sync(0xffffffffu, ss, o);
        float rn = rsqrtf(ss);
        kn[wid * 64 + 2 * lane]     = k0 * rn;
        kn[wid * 64 + 2 * lane + 1] = k1 * rn;
    }
    __syncthreads();

    const float* __restrict__ memb = memory + (size_t)b * MEM_ELEMS;

    // ---- Phase 1: S[n,h] = cos(mem_n, k_h) via mma (A = mem rows, B = kn) ----
    {
        // B fragments: kb[c] covers m-chunk c (8 elems) x 8 head-cols (6 valid)
        unsigned kb0[8], kb1[8];
#pragma unroll
        for (int c = 0; c < 8; c++) {
            float v0 = (g < HH) ? kn[g * 64 + c * 8 + t] : 0.0f;
            float v1 = (g < HH) ? kn[g * 64 + c * 8 + t + 4] : 0.0f;
            kb0[c] = __float_as_uint(v0);
            kb1[c] = __float_as_uint(v1);
        }

        float* tileF = tile + wid * 16 * TSTRIDE;
        float4* tf4 = (float4*)tileF;

        for (int j = 0; j < 8; j++) {
            const int n0 = wid * 16 + j * 256;
            // coalesced load: 16 rows x 64 floats
#pragma unroll
            for (int i = 0; i < 8; i++) {
                int idx = lane + i * 32;
                int row = idx >> 4, q = idx & 15;
                tf4[row * 17 + q] =
                    *(const float4*)(memb + (size_t)(n0 + row) * MM + q * 4);
            }
            __syncwarp();

            float acc[4] = {0.f, 0.f, 0.f, 0.f};
            float ss0 = 0.f, ss1 = 0.f;
#pragma unroll
            for (int c = 0; c < 8; c++) {
                float a0 = tileF[g * TSTRIDE + c * 8 + t];
                float a1 = tileF[(g + 8) * TSTRIDE + c * 8 + t];
                float a2 = tileF[g * TSTRIDE + c * 8 + t + 4];
                float a3 = tileF[(g + 8) * TSTRIDE + c * 8 + t + 4];
                ss0 += a0 * a0 + a2 * a2;
                ss1 += a1 * a1 + a3 * a3;
                unsigned af[4] = {__float_as_uint(a0), __float_as_uint(a1),
                                  __float_as_uint(a2), __float_as_uint(a3)};
                MMA_TF32(acc, af, kb0[c], kb1[c]);
            }
            // row-norm: reduce over the 4 lanes sharing g
            ss0 += __shfl_xor_sync(0xffffffffu, ss0, 1);
            ss0 += __shfl_xor_sync(0xffffffffu, ss0, 2);
            ss1 += __shfl_xor_sync(0xffffffffu, ss1, 1);
            ss1 += __shfl_xor_sync(0xffffffffu, ss1, 2);
            float rn0 = rsqrtf(ss0), rn1 = rsqrtf(ss1);

            scores2[(n0 + g) * SST + 2 * t]         = acc[0] * rn0;
            scores2[(n0 + g) * SST + 2 * t + 1]     = acc[1] * rn0;
            scores2[(n0 + g + 8) * SST + 2 * t]     = acc[2] * rn1;
            scores2[(n0 + g + 8) * SST + 2 * t + 1] = acc[3] * rn1;
            __syncwarp();
        }
    }
    __syncthreads();

    // ---- Phase 2: softmax over n, all heads fused ----
    {
        float mx[HH];
#pragma unroll
        for (int h = 0; h < HH; h++) mx[h] = -1e30f;
        for (int i = tid; i < NN; i += 512)
#pragma unroll
            for (int h = 0; h < HH; h++)
                mx[h] = fmaxf(mx[h], scores2[i * SST + h]);
#pragma unroll
        for (int h = 0; h < HH; h++) {
#pragma unroll
            for (int o = 16; o > 0; o >>= 1)
                mx[h] = fmaxf(mx[h], __shfl_xor_sync(0xffffffffu, mx[h], o));
        }
        if (lane == 0)
#pragma unroll
            for (int h = 0; h < HH; h++) red[h * 16 + wid] = mx[h];
        __syncthreads();
        if (wid == 0) {
#pragma unroll
            for (int h = 0; h < HH; h++) {
                float v = (lane < 16) ? red[h * 16 + lane] : -1e30f;
#pragma unroll
                for (int o = 8; o > 0; o >>= 1)
                    v = fmaxf(v, __shfl_xor_sync(0xffffffffu, v, o));
                if (lane == 0) redh[h] = v;
            }
        }
        __syncthreads();

        float bmx[HH], sum[HH];
#pragma unroll
        for (int h = 0; h < HH; h++) { bmx[h] = redh[h]; sum[h] = 0.0f; }
        for (int i = tid; i < NN; i += 512) {
#pragma unroll
            for (int h = 0; h < HH; h++) {
                float e = __expf(scores2[i * SST + h] - bmx[h]);
                scores2[i * SST + h] = e;
                sum[h] += e;
            }
        }
#pragma unroll
        for (int h = 0; h < HH; h++) {
#pragma unroll
            for (int o = 16; o > 0; o >>= 1)
                sum[h] += __shfl_xor_sync(0xffffffffu, sum[h], o);
        }
        if (lane == 0)
#pragma unroll
            for (int h = 0; h < HH; h++) red[h * 16 + wid] = sum[h];
        __syncthreads();
        if (wid == 0) {
#pragma unroll
            for (int h = 0; h < HH; h++) {
                float v = (lane < 16) ? red[h * 16 + lane] : 0.0f;
#pragma unroll
                for (int o = 8; o > 0; o >>= 1)
                    v += __shfl_xor_sync(0xffffffffu, v, o);
                if (lane == 0) redh[h] = v;
            }
        }
        __syncthreads();

        float inv[HH];
#pragma unroll
        for (int h = 0; h < HH; h++) inv[h] = 1.0f / redh[h];
        for (int i = tid; i < NN; i += 512) {
#pragma unroll
            for (int h = 0; h < HH; h++) {
                float wv = scores2[i * SST + h] * inv[h];
                scores2[i * SST + h] = wv;
                out_w[(size_t)b * (HH * NN) + h * NN + i] = wv;
            }
        }
    }
    __syncthreads();

    // ---- Phase 3: erase/add einsums via mma, fused update ----
    {
        // B fragments from e/a: rows = head (k, 6 valid of 8), cols = m
        unsigned eb0[8], eb1[8], ab0[8], ab1[8];
#pragma unroll
        for (int mb = 0; mb < 8; mb++) {
            eb0[mb] = __float_as_uint(esm[t * 64 + mb * 8 + g]);   // t<4 always valid
            ab0[mb] = __float_as_uint(asm_[t * 64 + mb * 8 + g]);
            eb1[mb] = __float_as_uint((t < 2) ? esm[(t + 4) * 64 + mb * 8 + g] : 0.0f);
            ab1[mb] = __float_as_uint((t < 2) ? asm_[(t + 4) * 64 + mb * 8 + g] : 0.0f);
        }

        float* outm = out_mem + (size_t)b * MEM_ELEMS;

        for (int j = 0; j < 8; j++) {
            const int n0 = wid * 16 + j * 256;
            // A fragment: w_new rows (scores2 cols 6,7 are exact zeros)
            unsigned af[4];
            af[0] = __float_as_uint(scores2[(n0 + g) * SST + t]);
            af[1] = __float_as_uint(scores2[(n0 + g + 8) * SST + t]);
            af[2] = __float_as_uint(scores2[(n0 + g) * SST + t + 4]);
            af[3] = __float_as_uint(scores2[(n0 + g + 8) * SST + t + 4]);

            float er[8][4], ad[8][4];
#pragma unroll
            for (int mb = 0; mb < 8; mb++) {
#pragma unroll
                for (int q = 0; q < 4; q++) { er[mb][q] = 0.f; ad[mb][q] = 0.f; }
                MMA_TF32(er[mb], af, eb0[mb], eb1[mb]);
                MMA_TF32(ad[mb], af, ab0[mb], ab1[mb]);
            }

            const float* mrow0 = memb + (size_t)(n0 + g) * MM;
            const float* mrow1 = memb + (size_t)(n0 + g + 8) * MM;
            float* orow0 = outm + (size_t)(n0 + g) * MM;
            float* orow1 = outm + (size_t)(n0 + g + 8) * MM;
#pragma unroll
            for (int mb = 0; mb < 8; mb++) {
                float2 m0v = *(const float2*)(mrow0 + mb * 8 + 2 * t);
                float2 m1v = *(const float2*)(mrow1 + mb * 8 + 2 * t);
                float2 o0, o1;
                o0.x = m0v.x + (ad[mb][0] - m0v.x * m0v.x * er[mb][0]);
                o0.y = m0v.y + (ad[mb][1] - m0v.y * m0v.y * er[mb][1]);
                o1.x = m1v.x + (ad[mb][2] - m1v.x * m1v.x * er[mb][2]);
                o1.y = m1v.y + (ad[mb][3] - m1v.y * m1v.y * er[mb][3]);
                *(float2*)(orow0 + mb * 8 + 2 * t) = o0;
                *(float2*)(orow1 + mb * 8 + 2 * t) = o1;
            }
        }
    }
}

// ---------------------------------------------------------------------------
extern "C" void kernel_launch(void* const* d_in, const int* in_sizes, int n_in,
                              void* d_out, int out_size)
{
    const float* inputs = (const float*)d_in[0];
    const float* memory = (const float*)d_in[1];
    const float* w      = (const float*)d_in[2];
    const float* Wk     = (const float*)d_in[3];
    const float* bk     = (const float*)d_in[4];
    const float* We     = (const float*)d_in[5];
    const float* be     = (const float*)d_in[6];
    const float* Wa     = (const float*)d_in[7];
    const float* ba     = (const float*)d_in[8];

    float* out     = (float*)d_out;
    float* out_mem = out;                       // new_memory [B,N,M]
    float* out_w   = out + OUT_MEM_TOTAL;       // w_new      [B,H,N]

    dim3 g1(4, 18, SPLITK);
    gemm_kernel<<<g1, 128>>>(w, inputs, Wk, We, Wa);

    reduce_act_kernel<<<(BB * Y_N) / 256, 256>>>(bk, be, ba);

    const int smem_bytes = ATTN_SMEM_FLOATS * (int)sizeof(float);
    cudaFuncSetAttribute(attn_update_kernel,
                         cudaFuncAttributeMaxDynamicSharedMemorySize, smem_bytes);
    attn_update_kernel<<<BB, 512, smem_bytes>>>(memory, out_mem, out_w);
}

// round 4
// speedup vs baseline: 1.5613x; 1.0344x over previous
#include <cuda_runtime.h>
#include <math.h>

// Problem constants
#define BB    256
#define HH    6
#define NN    2048
#define MM    64
#define DIN   128
#define WFLAT 12288          // H*N
#define DCAT  12416
#define DOUT  384
#define Y_N   1152           // 3*DOUT
#define MEM_ELEMS 131072     // N*M per batch
#define OUT_MEM_TOTAL 33554432  // B*N*M

// GEMM config: K-tiles of 32 floats; 388 tiles total; uneven split over 12
#define SPLITK 12
#define BKT 32
#define NKT_TOTAL 388        // 12416 / 32
#define BMT 64
#define BNT 64
#define ASTR 36              // A tile stride (32 + 4 pad) -> LDSM conflict-free
#define BSTR 72              // B tile stride (64 + 8 pad) -> frag LDS conflict-free

// Scratch (static device memory; no allocation)
__device__ float g_Ypart[SPLITK * (size_t)BB * Y_N];  // 14.2 MB
__device__ float g_Ks[BB * DOUT];
__device__ float g_Es[BB * DOUT];
__device__ float g_As[BB * DOUT];

__device__ __forceinline__ float f2tf(float f) {
    unsigned u;
    asm("cvt.rna.tf32.f32 %0, %1;" : "=r"(u) : "f"(f));
    return __uint_as_float(u);
}

__device__ __forceinline__ unsigned s2u(const void* p) {
    return (unsigned)__cvta_generic_to_shared(p);
}

#define MMA_TF32(c, a, b0, b1)                                                     \
    asm volatile(                                                                  \
        "mma.sync.aligned.m16n8k8.row.col.f32.tf32.tf32.f32 "                      \
        "{%0,%1,%2,%3},{%4,%5,%6,%7},{%8,%9},{%0,%1,%2,%3};"                       \
        : "+f"(c[0]), "+f"(c[1]), "+f"(c[2]), "+f"(c[3])                           \
        : "r"(a[0]), "r"(a[1]), "r"(a[2]), "r"(a[3]), "r"(b0), "r"(b1))

#define LDSM_X4(r, addr)                                                           \
    asm volatile("ldmatrix.sync.aligned.m8n8.x4.shared.b16 {%0,%1,%2,%3}, [%4];"   \
                 : "=r"(r[0]), "=r"(r[1]), "=r"(r[2]), "=r"(r[3]) : "r"(addr))

// ---------------------------------------------------------------------------
// K1: split-K tf32 GEMM  Y[256,1152] = x[256,12416] @ [Wk|We|Wa]
// grid (4, 18, 12), 128 threads. A frags via ldmatrix, BKT=32.
// ---------------------------------------------------------------------------
__global__ __launch_bounds__(128) void gemm_kernel(
    const float* __restrict__ xw, const float* __restrict__ xin,
    const float* __restrict__ Wk, const float* __restrict__ We,
    const float* __restrict__ Wa)
{
    __shared__ float As[2][BMT * ASTR];   // 64 x 32 (+pad)
    __shared__ float Bs[2][BKT * BSTR];   // 32 x 64 (+pad)

    const int tid = threadIdx.x;
    const int mt = blockIdx.x, nt = blockIdx.y, z = blockIdx.z;
    const int m0 = mt * BMT;
    const int mat = nt / 6;
    const int n0col = (nt % 6) * BNT;
    const float* __restrict__ Wp = (mat == 0) ? Wk : ((mat == 1) ? We : Wa);

    // Uneven split-K: first 4 z's get 33 tiles, rest 32 (total 388)
    const int baseT = z * 32 + min(z, 4);
    const int cnt   = 32 + (z < 4 ? 1 : 0);
    const int k0    = baseT * BKT;

    const int wid = tid >> 5, lane = tid & 31;
    const int g = lane >> 2, t = lane & 3;
    const int wm = (wid & 1) * 32, wn = (wid >> 1) * 32;

    // LDSM per-lane address component (floats): rows (lane&15), k-half (lane>>4)*4
    const int aRowOff = (lane & 15) * ASTR + (lane >> 4) * 4;
    const unsigned sAs0 = s2u(&As[0][0]);
    const unsigned sAs1 = s2u(&As[1][0]);

    // Global-load coordinates
    const int arow = tid >> 3;          // 0..15 base rows (4 batches of 16)
    const int akf4 = (tid & 7) * 4;     // k offset in floats
    const int bkr  = tid >> 4;          // 0..7 base k rows (4 batches of 8)
    const int bnf4 = (tid & 15) * 4;    // n offset

    float acc[2][4][4];
#pragma unroll
    for (int i = 0; i < 2; i++)
#pragma unroll
        for (int j = 0; j < 4; j++)
#pragma unroll
            for (int q = 0; q < 4; q++) acc[i][j][q] = 0.0f;

    float4 ar[4], br[4];

#define GLOAD(it)                                                                  \
    do {                                                                           \
        int kb = k0 + (it) * BKT;                                                  \
        _Pragma("unroll")                                                          \
        for (int i = 0; i < 4; i++) {                                              \
            int row = arow + i * 16;                                               \
            int kg = kb + akf4;                                                    \
            if (kg < WFLAT)                                                        \
                ar[i] = *(const float4*)(xw + (size_t)(m0 + row) * WFLAT + kg);    \
            else                                                                   \
                ar[i] = *(const float4*)(xin + (size_t)(m0 + row) * DIN +          \
                                         (kg - WFLAT));                            \
        }                                                                          \
        _Pragma("unroll")                                                          \
        for (int i = 0; i < 4; i++) {                                              \
            int kr = bkr + i * 8;                                                  \
            br[i] = *(const float4*)(Wp + (size_t)(kb + kr) * DOUT + n0col + bnf4);\
        }                                                                          \
    } while (0)

#define STS(bufb)                                                                  \
    do {                                                                           \
        _Pragma("unroll")                                                          \
        for (int i = 0; i < 4; i++) {                                              \
            float4 v;                                                              \
            v.x = f2tf(ar[i].x); v.y = f2tf(ar[i].y);                              \
            v.z = f2tf(ar[i].z); v.w = f2tf(ar[i].w);                              \
            *(float4*)&As[bufb][(arow + i * 16) * ASTR + akf4] = v;                \
        }                                                                          \
        _Pragma("unroll")                                                          \
        for (int i = 0; i < 4; i++) {                                              \
            float4 v;                                                              \
            v.x = f2tf(br[i].x); v.y = f2tf(br[i].y);                              \
            v.z = f2tf(br[i].z); v.w = f2tf(br[i].w);                              \
            *(float4*)&Bs[bufb][(bkr + i * 8) * BSTR + bnf4] = v;                  \
        }                                                                          \
    } while (0)

    GLOAD(0);
    STS(0);

    for (int it = 0; it < cnt; ++it) {
        __syncthreads();
        if (it + 1 < cnt) GLOAD(it + 1);

        const int bf = it & 1;
        const unsigned sA = (bf == 0) ? sAs0 : sAs1;
#pragma unroll
        for (int ko = 0; ko < BKT; ko += 8) {
            unsigned af[2][4];
#pragma unroll
            for (int mf = 0; mf < 2; mf++) {
                unsigned addr = sA + 4u * ((wm + mf * 16) * ASTR + aRowOff + ko);
                LDSM_X4(af[mf], addr);
            }
            unsigned bfr[4][2];
#pragma unroll
            for (int nf = 0; nf < 4; nf++) {
                int c0 = wn + nf * 8 + g;
                bfr[nf][0] = __float_as_uint(Bs[bf][(ko + t) * BSTR + c0]);
                bfr[nf][1] = __float_as_uint(Bs[bf][(ko + t + 4) * BSTR + c0]);
            }
#pragma unroll
            for (int mf = 0; mf < 2; mf++)
#pragma unroll
                for (int nf = 0; nf < 4; nf++)
                    MMA_TF32(acc[mf][nf], af[mf], bfr[nf][0], bfr[nf][1]);
        }

        if (it + 1 < cnt) STS((it + 1) & 1);
    }

    // Epilogue: write partial tile (deterministic, no atomics)
    float* yp = g_Ypart + (size_t)z * (BB * Y_N);
#pragma unroll
    for (int mf = 0; mf < 2; mf++) {
#pragma unroll
        for (int nf = 0; nf < 4; nf++) {
            int row = m0 + wm + mf * 16 + g;
            int col = nt * BNT + wn + nf * 8 + 2 * t;
            float2 v0 = make_float2(acc[mf][nf][0], acc[mf][nf][1]);
            float2 v1 = make_float2(acc[mf][nf][2], acc[mf][nf][3]);
            *(float2*)(yp + (size_t)row * Y_N + col) = v0;
            *(float2*)(yp + (size_t)(row + 8) * Y_N + col) = v1;
        }
    }
#undef GLOAD
#undef STS
}

// ---------------------------------------------------------------------------
// K1b: reduce split-K partials, add bias, apply sigmoid for e/a
// ---------------------------------------------------------------------------
__global__ void reduce_act_kernel(const float* __restrict__ bk,
                                  const float* __restrict__ be,
                                  const float* __restrict__ ba)
{
    int idx = blockIdx.x * blockDim.x + threadIdx.x;
    float s = 0.0f;
#pragma unroll
    for (int z = 0; z < SPLITK; z++)
        s += g_Ypart[(size_t)z * (BB * Y_N) + idx];
    int row = idx / Y_N;
    int col = idx - row * Y_N;
    int mat = col / DOUT;
    int c = col - mat * DOUT;
    if (mat == 0) {
        g_Ks[row * DOUT + c] = s + bk[c];
    } else if (mat == 1) {
        float v = s + be[c];
        g_Es[row * DOUT + c] = 1.0f / (1.0f + __expf(-v));
    } else {
        float v = s + ba[c];
        g_As[row * DOUT + c] = 1.0f / (1.0f + __expf(-v));
    }
}

// ---------------------------------------------------------------------------
// K2: per-batch fused addressing + softmax + update, tensor-core einsums.
// grid 256, 256 threads (8 warps), ~110.7 KB smem -> 2 CTAs/SM, one wave.
// ---------------------------------------------------------------------------
#define SST 9        // scores row stride (floats): conflict-free both axes
#define TSTRIDE 68   // per-warp tile row stride (floats) = 17 float4
#define NWARP 8
#define ATTN_SMEM_FLOATS (NN * SST + NWARP * 16 * TSTRIDE + 3 * DOUT + HH * NWARP + 8)

__global__ __launch_bounds__(256, 2) void attn_update_kernel(
    const float* __restrict__ memory, float* __restrict__ out_mem,
    float* __restrict__ out_w)
{
    extern __shared__ float sm[];
    float* scores2 = sm;                            // 2048*9
    float* tile    = scores2 + NN * SST;            // 8 warps * 16 * 68
    float* kn      = tile + NWARP * 16 * TSTRIDE;   // 384
    float* esm     = kn + DOUT;                     // 384
    float* asm_    = esm + DOUT;                    // 384
    float* red     = asm_ + DOUT;                   // 48
    float* redh    = red + HH * NWARP;              // 8

    const int b = blockIdx.x;
    const int tid = threadIdx.x, wid = tid >> 5, lane = tid & 31;
    const int g = lane >> 2, t = lane & 3;

    // ---- Phase 0: load e/a, compute normalized k ----
    for (int i = tid; i < DOUT; i += 256) {
        esm[i]  = g_Es[b * DOUT + i];
        asm_[i] = g_As[b * DOUT + i];
    }
    if (wid < HH) {
        float k0 = g_Ks[b * DOUT + wid * 64 + 2 * lane];
        float k1 = g_Ks[b * DOUT + wid * 64 + 2 * lane + 1];
        float ss = k0 * k0 + k1 * k1;
#pragma unroll
        for (int o = 16; o > 0; o >>= 1) ss += __shfl_xor_sync(0xffffffffu, ss, o);
        float rn = rsqrtf(ss);
        kn[wid * 64 + 2 * lane]     = k0 * rn;
        kn[wid * 64 + 2 * lane + 1] = k1 * rn;
    }
    __syncthreads();

    const float* __restrict__ memb = memory + (size_t)b * MEM_ELEMS;

    // ---- Phase 1: S[n,h] = cos(mem_n, k_h) via mma ----
    {
        unsigned kb0[8], kb1[8];
#pragma unroll
        for (int c = 0; c < 8; c++) {
            float v0 = (g < HH) ? kn[g * 64 + c * 8 + t] : 0.0f;
            float v1 = (g < HH) ? kn[g * 64 + c * 8 + t + 4] : 0.0f;
            kb0[c] = __float_as_uint(v0);
            kb1[c] = __float_as_uint(v1);
        }

        float* tileF = tile + wid * 16 * TSTRIDE;
        float4* tf4 = (float4*)tileF;

        for (int j = 0; j < 16; j++) {
            const int n0 = wid * 16 + j * 128;
#pragma unroll
            for (int i = 0; i < 8; i++) {
                int idx = lane + i * 32;
                int row = idx >> 4, q = idx & 15;
                tf4[row * 17 + q] =
                    *(const float4*)(memb + (size_t)(n0 + row) * MM + q * 4);
            }
            __syncwarp();

            float acc[4] = {0.f, 0.f, 0.f, 0.f};
            float ss0 = 0.f, ss1 = 0.f;
#pragma unroll
            for (int c = 0; c < 8; c++) {
                float a0 = tileF[g * TSTRIDE + c * 8 + t];
                float a1 = tileF[(g + 8) * TSTRIDE + c * 8 + t];
                float a2 = tileF[g * TSTRIDE + c * 8 + t + 4];
                float a3 = tileF[(g + 8) * TSTRIDE + c * 8 + t + 4];
                ss0 += a0 * a0 + a2 * a2;
                ss1 += a1 * a1 + a3 * a3;
                unsigned af[4] = {__float_as_uint(a0), __float_as_uint(a1),
                                  __float_as_uint(a2), __float_as_uint(a3)};
                MMA_TF32(acc, af, kb0[c], kb1[c]);
            }
            ss0 += __shfl_xor_sync(0xffffffffu, ss0, 1);
            ss0 += __shfl_xor_sync(0xffffffffu, ss0, 2);
            ss1 += __shfl_xor_sync(0xffffffffu, ss1, 1);
            ss1 += __shfl_xor_sync(0xffffffffu, ss1, 2);
            float rn0 = rsqrtf(ss0), rn1 = rsqrtf(ss1);

            scores2[(n0 + g) * SST + 2 * t]         = acc[0] * rn0;
            scores2[(n0 + g) * SST + 2 * t + 1]     = acc[1] * rn0;
            scores2[(n0 + g + 8) * SST + 2 * t]     = acc[2] * rn1;
            scores2[(n0 + g + 8) * SST + 2 * t + 1] = acc[3] * rn1;
            __syncwarp();
        }
    }
    __syncthreads();

    // ---- Phase 2: softmax over n, all heads fused ----
    {
        float mx[HH];
#pragma unroll
        for (int h = 0; h < HH; h++) mx[h] = -1e30f;
        for (int i = tid; i < NN; i += 256)
#pragma unroll
            for (int h = 0; h < HH; h++)
                mx[h] = fmaxf(mx[h], scores2[i * SST + h]);
#pragma unroll
        for (int h = 0; h < HH; h++) {
#pragma unroll
            for (int o = 16; o > 0; o >>= 1)
                mx[h] = fmaxf(mx[h], __shfl_xor_sync(0xffffffffu, mx[h], o));
        }
        if (lane == 0)
#pragma unroll
            for (int h = 0; h < HH; h++) red[h * NWARP + wid] = mx[h];
        __syncthreads();
        if (wid == 0) {
#pragma unroll
            for (int h = 0; h < HH; h++) {
                float v = (lane < NWARP) ? red[h * NWARP + lane] : -1e30f;
#pragma unroll
                for (int o = 4; o > 0; o >>= 1)
                    v = fmaxf(v, __shfl_xor_sync(0xffffffffu, v, o));
                if (lane == 0) redh[h] = v;
            }
        }
        __syncthreads();

        float bmx[HH], sum[HH];
#pragma unroll
        for (int h = 0; h < HH; h++) { bmx[h] = redh[h]; sum[h] = 0.0f; }
        for (int i = tid; i < NN; i += 256) {
#pragma unroll
            for (int h = 0; h < HH; h++) {
                float e = __expf(scores2[i * SST + h] - bmx[h]);
                scores2[i * SST + h] = e;
                sum[h] += e;
            }
        }
#pragma unroll
        for (int h = 0; h < HH; h++) {
#pragma unroll
            for (int o = 16; o > 0; o >>= 1)
                sum[h] += __shfl_xor_sync(0xffffffffu, sum[h], o);
        }
        if (lane == 0)
#pragma unroll
            for (int h = 0; h < HH; h++) red[h * NWARP + wid] = sum[h];
        __syncthreads();
        if (wid == 0) {
#pragma unroll
            for (int h = 0; h < HH; h++) {
                float v = (lane < NWARP) ? red[h * NWARP + lane] : 0.0f;
#pragma unroll
                for (int o = 4; o > 0; o >>= 1)
                    v += __shfl_xor_sync(0xffffffffu, v, o);
                if (lane == 0) redh[h] = v;
            }
        }
        __syncthreads();

        float inv[HH];
#pragma unroll
        for (int h = 0; h < HH; h++) inv[h] = 1.0f / redh[h];
        for (int i = tid; i < NN; i += 256) {
#pragma unroll
            for (int h = 0; h < HH; h++) {
                float wv = scores2[i * SST + h] * inv[h];
                scores2[i * SST + h] = wv;
                out_w[(size_t)b * (HH * NN) + h * NN + i] = wv;
            }
        }
    }
    __syncthreads();

    // ---- Phase 3: erase/add einsums via mma, fused update ----
    {
        unsigned eb0[8], eb1[8], ab0[8], ab1[8];
#pragma unroll
        for (int mb = 0; mb < 8; mb++) {
            eb0[mb] = __float_as_uint(esm[t * 64 + mb * 8 + g]);
            ab0[mb] = __float_as_uint(asm_[t * 64 + mb * 8 + g]);
            eb1[mb] = __float_as_uint((t < 2) ? esm[(t + 4) * 64 + mb * 8 + g] : 0.0f);
            ab1[mb] = __float_as_uint((t < 2) ? asm_[(t + 4) * 64 + mb * 8 + g] : 0.0f);
        }

        float* outm = out_mem + (size_t)b * MEM_ELEMS;

        for (int j = 0; j < 16; j++) {
            const int n0 = wid * 16 + j * 128;
            unsigned af[4];
            af[0] = __float_as_uint(scores2[(n0 + g) * SST + t]);
            af[1] = __float_as_uint(scores2[(n0 + g + 8) * SST + t]);
            af[2] = __float_as_uint(scores2[(n0 + g) * SST + t + 4]);
            af[3] = __float_as_uint(scores2[(n0 + g + 8) * SST + t + 4]);

            float er[8][4], ad[8][4];
#pragma unroll
            for (int mb = 0; mb < 8; mb++) {
#pragma unroll
                for (int q = 0; q < 4; q++) { er[mb][q] = 0.f; ad[mb][q] = 0.f; }
                MMA_TF32(er[mb], af, eb0[mb], eb1[mb]);
                MMA_TF32(ad[mb], af, ab0[mb], ab1[mb]);
            }

            const float* mrow0 = memb + (size_t)(n0 + g) * MM;
            const float* mrow1 = memb + (size_t)(n0 + g + 8) * MM;
            float* orow0 = outm + (size_t)(n0 + g) * MM;
            float* orow1 = outm + (size_t)(n0 + g + 8) * MM;
#pragma unroll
            for (int mb = 0; mb < 8; mb++) {
                float2 m0v = *(const float2*)(mrow0 + mb * 8 + 2 * t);
                float2 m1v = *(const float2*)(mrow1 + mb * 8 + 2 * t);
                float2 o0, o1;
                o0.x = m0v.x + (ad[mb][0] - m0v.x * m0v.x * er[mb][0]);
                o0.y = m0v.y + (ad[mb][1] - m0v.y * m0v.y * er[mb][1]);
                o1.x = m1v.x + (ad[mb][2] - m1v.x * m1v.x * er[mb][2]);
                o1.y = m1v.y + (ad[mb][3] - m1v.y * m1v.y * er[mb][3]);
                *(float2*)(orow0 + mb * 8 + 2 * t) = o0;
                *(float2*)(orow1 + mb * 8 + 2 * t) = o1;
            }
        }
    }
}

// ---------------------------------------------------------------------------
extern "C" void kernel_launch(void* const* d_in, const int* in_sizes, int n_in,
                              void* d_out, int out_size)
{
    const float* inputs = (const float*)d_in[0];
    const float* memory = (const float*)d_in[1];
    const float* w      = (const float*)d_in[2];
    const float* Wk     = (const float*)d_in[3];
    const float* bk     = (const float*)d_in[4];
    const float* We     = (const float*)d_in[5];
    const float* be     = (const float*)d_in[6];
    const float* Wa     = (const float*)d_in[7];
    const float* ba     = (const float*)d_in[8];

    float* out     = (float*)d_out;
    float* out_mem = out;                       // new_memory [B,N,M]
    float* out_w   = out + OUT_MEM_TOTAL;       // w_new      [B,H,N]

    dim3 g1(4, 18, SPLITK);
    gemm_kernel<<<g1, 128>>>(w, inputs, Wk, We, Wa);

    reduce_act_kernel<<<(BB * Y_N) / 256, 256>>>(bk, be, ba);

    const int smem_bytes = ATTN_SMEM_FLOATS * (int)sizeof(float);
    cudaFuncSetAttribute(attn_update_kernel,
                         cudaFuncAttributeMaxDynamicSharedMemorySize, smem_bytes);
    attn_update_kernel<<<BB, 256, smem_bytes>>>(memory, out_mem, out_w);
}